// round 11
// baseline (speedup 1.0000x reference)
#include <cuda_runtime.h>

#define NN 20000
#define EE 400000
#define CC 16
#define HH 64
#define NB 8
#define NL 3
#define TABN 1024
#define SLOTS 64
#define RMIN 0.5f
#define RCUT 5.0f
#define TABTHREADS (NL * TABN * 32)      // 98304, warp-per-knot
#define PREPTOTAL  (EE + TABTHREADS)     // edge region first (warp-aligned split)

__device__ float  g_xs[2 * NN * CC];               // scalar channel, double buffered
__device__ float4 g_Rtab4[NL * TABN * 8];          // [layer][knot][q]: {Rk[2q],Rk1[2q],Rk[2q+1],Rk1[2q+1]} — 128KB/layer
__device__ int    g_cnt[NN];                       // zero at start of every replay (see layer2)
__device__ float2 g_rec[(size_t)NN * SLOTS];       // {srcoff = src*CC, t}

__device__ __forceinline__ float sspf(float v) {
    // softplus(v) - ln2, fast: |abs err| ~1e-7
    float z = __expf(-fabsf(v));
    return fmaxf(v, 0.f) + __logf(1.f + z) - 0.69314718055994531f;
}

// ---------------------------------------------------------------------------
// Fused prep:
//   tid <  EE : build slotted CSR record {src*CC, t}; first NN*CC threads
//               also init xs buf0 from embedding.
//   tid >= EE : warp per (layer, knot) radial table entry.
// g_cnt is guaranteed zero on entry (static init first run; layer2 re-zeroes).
// ---------------------------------------------------------------------------
__global__ void __launch_bounds__(256)
prep_kernel(const int* __restrict__ eidx, const float* __restrict__ dist,
            const int* __restrict__ species, const float* __restrict__ Wemb,
            const float* __restrict__ W1, const float* __restrict__ W2) {
    int tid = blockIdx.x * 256 + threadIdx.x;

    if (tid < EE) {
        if (tid < NN * CC) {
            int n = tid >> 4, c = tid & 15;
            g_xs[n * CC + c] = Wemb[species[n] * CC + c];
        }
        float r = dist[tid];
        if (!(r < RCUT)) return;
        int src = eidx[2 * tid];
        int dst = eidx[2 * tid + 1];
        int pos = atomicAdd(&g_cnt[dst], 1);
        if (pos >= SLOTS) return;   // statistically unreachable (Poisson ~16.4)
        float t = (r - RMIN) * ((float)(TABN - 1) / (RCUT - RMIN));
        t = fminf(fmaxf(t, 0.f), (float)(TABN - 1) - 1e-3f);
        g_rec[(size_t)dst * SLOTS + pos] = make_float2(__int_as_float(src * CC), t);
        return;
    }

    // ---- table region (whole warps: EE % 32 == 0)
    int gw   = (tid - EE) >> 5;
    int lane = threadIdx.x & 31;
    if (gw >= NL * TABN) return;
    int layer = gw / TABN;
    int k     = gw % TABN;

    __shared__ float sa[8][64];
    float* a = sa[(threadIdx.x >> 5)];

    float r = RMIN + (RCUT - RMIN) * ((float)k / (float)(TABN - 1));
    float u = r / RCUT;
    float u3 = u * u * u;
    float u6 = u3 * u3;
    float env = 1.f - 28.f * u6 + 48.f * u6 * u - 21.f * u6 * u * u;
    if (k == TABN - 1) env = 0.f;
    float pref = sqrtf(2.f / RCUT) / r * env;
    float eb[NB];
#pragma unroll
    for (int n = 0; n < NB; n++)
        eb[n] = pref * sinf((float)(n + 1) * 3.14159265358979323846f * r / RCUT);

    const float* w1 = W1 + (size_t)layer * NB * HH;
    const float* w2 = W2 + (size_t)layer * HH * (2 * CC);
#pragma unroll
    for (int rep = 0; rep < 2; rep++) {
        int j = lane + rep * 32;
        float h = 0.f;
#pragma unroll
        for (int n = 0; n < NB; n++) h = fmaf(eb[n], w1[n * HH + j], h);
        a[j] = sspf(h);
    }
    __syncwarp();

    if (lane < CC) {
        int c = lane;
        float acc = 0.f;
#pragma unroll
        for (int j = 0; j < HH; j++)
            acc = fmaf(a[j], w2[j * 32 + c] + w2[j * 32 + 16 + c], acc);
        float val = acc * 0.22360679774997896f;   // deg_norm = 1/sqrt(20)
        float* T = (float*)(g_Rtab4 + ((size_t)layer * TABN) * 8);
        int q = c >> 1, pos = (c & 1) * 2;
        T[(k * 8 + q) * 4 + pos] = val;                       // Rk[c]
        if (k > 0) T[((k - 1) * 8 + q) * 4 + pos + 1] = val;  // Rk-1's next
    }
}

// ---------------------------------------------------------------------------
// Edge-loop body: lane = eslot*8 + q. Per block of 16 edges (4 per slot),
// ALWAYS issue 4 predicated rec loads then 8 independent tab/xin loads.
// Out-of-range edges clamp the rec index to 0 and zero the lerped weight,
// so every node runs the full-MLP path regardless of degree.
// ---------------------------------------------------------------------------
__device__ __forceinline__ void
aggregate(const float* __restrict__ xin, const float4* __restrict__ tab,
          const float2* __restrict__ rec, int cnt, int eslot, int q,
          float& acc0, float& acc1) {
    float a0 = 0.f, a1 = 0.f, b0 = 0.f, b1 = 0.f;
    float c0 = 0.f, c1 = 0.f, d0 = 0.f, d1 = 0.f;
    for (int base = 0; base < cnt; base += 16) {
        int e0 = base + eslot, e1 = e0 + 4, e2 = e0 + 8, e3 = e0 + 12;
        bool v0 = e0 < cnt, v1 = e1 < cnt, v2 = e2 < cnt, v3 = e3 < cnt;
        float2 rA = rec[v0 ? e0 : 0];
        float2 rB = rec[v1 ? e1 : 0];
        float2 rC = rec[v2 ? e2 : 0];
        float2 rD = rec[v3 ? e3 : 0];
        int   sA = __float_as_int(rA.x), sB = __float_as_int(rB.x);
        int   sC = __float_as_int(rC.x), sD = __float_as_int(rD.x);
        int   kA = (int)rA.y, kB = (int)rB.y, kC = (int)rC.y, kD = (int)rD.y;
        float fA = rA.y - (float)kA, fB = rB.y - (float)kB;
        float fC = rC.y - (float)kC, fD = rD.y - (float)kD;
        float4 pA = tab[kA * 8 + q], pB = tab[kB * 8 + q];
        float4 pC = tab[kC * 8 + q], pD = tab[kD * 8 + q];
        const float2 xA = *(const float2*)(xin + sA + 2 * q);
        const float2 xB = *(const float2*)(xin + sB + 2 * q);
        const float2 xC = *(const float2*)(xin + sC + 2 * q);
        const float2 xD = *(const float2*)(xin + sD + 2 * q);
        float wA0 = v0 ? fmaf(fA, pA.y - pA.x, pA.x) : 0.f;
        float wA1 = v0 ? fmaf(fA, pA.w - pA.z, pA.z) : 0.f;
        float wB0 = v1 ? fmaf(fB, pB.y - pB.x, pB.x) : 0.f;
        float wB1 = v1 ? fmaf(fB, pB.w - pB.z, pB.z) : 0.f;
        float wC0 = v2 ? fmaf(fC, pC.y - pC.x, pC.x) : 0.f;
        float wC1 = v2 ? fmaf(fC, pC.w - pC.z, pC.z) : 0.f;
        float wD0 = v3 ? fmaf(fD, pD.y - pD.x, pD.x) : 0.f;
        float wD1 = v3 ? fmaf(fD, pD.w - pD.z, pD.z) : 0.f;
        a0 = fmaf(wA0, xA.x, a0);
        a1 = fmaf(wA1, xA.y, a1);
        b0 = fmaf(wB0, xB.x, b0);
        b1 = fmaf(wB1, xB.y, b1);
        c0 = fmaf(wC0, xC.x, c0);
        c1 = fmaf(wC1, xC.y, c1);
        d0 = fmaf(wD0, xD.x, d0);
        d1 = fmaf(wD1, xD.y, d1);
    }
    acc0 = (a0 + b0) + (c0 + d0);
    acc1 = (a1 + b1) + (c1 + d1);
    // reduce across the 4 edge-slots (lanes q, q+8, q+16, q+24)
    acc0 += __shfl_xor_sync(0xffffffffu, acc0, 8);
    acc1 += __shfl_xor_sync(0xffffffffu, acc1, 8);
    acc0 += __shfl_xor_sync(0xffffffffu, acc0, 16);
    acc1 += __shfl_xor_sync(0xffffffffu, acc1, 16);
}

// ---------------------------------------------------------------------------
// Scalar layer, warp per node: lanes = 4 edge-slots x 8 channel-pairs.
//   agg[c] = sum_e w_e[c] * xs_in[src_e][c];  xs_out = ssp(agg @ Wmix[l,0])
// ---------------------------------------------------------------------------
__global__ void __launch_bounds__(256)
layer_kernel(int layer, int rd, const float* __restrict__ Wmix) {
    __shared__ float sW[CC * CC];
    for (int i = threadIdx.x; i < 256; i += 256) sW[i] = Wmix[layer * 768 + i];
    __syncthreads();

    const unsigned FULL = 0xffffffffu;
    int lane  = threadIdx.x & 31;
    int eslot = lane >> 3;
    int q     = lane & 7;
    int n = blockIdx.x * 8 + (threadIdx.x >> 5);   // NN = 2500 * 8 exactly

    const float*  xin  = g_xs + rd * (NN * CC);
    float*        xout = g_xs + (1 - rd) * (NN * CC);
    const float4* tab  = g_Rtab4 + (size_t)layer * TABN * 8;
    const float2* rec  = g_rec + (size_t)n * SLOTS;
    int cnt = min(g_cnt[n], SLOTS);

    float acc0 = 0.f, acc1 = 0.f;
    if (cnt > 0) aggregate(xin, tab, rec, cnt, eslot, q, acc0, acc1);

    // mix: s[d] = sum_cc agg[cc] * W[cc][d]; agg[cc] lives in lane cc>>1 (eslot0)
    float s0 = 0.f, s1 = 0.f;
#pragma unroll
    for (int cc = 0; cc < 16; cc++) {
        float v = __shfl_sync(FULL, (cc & 1) ? acc1 : acc0, cc >> 1);
        s0 = fmaf(v, sW[cc * 16 + 2 * q],     s0);
        s1 = fmaf(v, sW[cc * 16 + 2 * q + 1], s1);
    }
    if (eslot == 0)
        *(float2*)(xout + n * CC + 2 * q) = make_float2(sspf(s0), sspf(s1));
}

// ---------------------------------------------------------------------------
// Layer 2 fused with readout: out[n] = ssp(ssp(agg@Wmix[2,0]) @ Wr1) @ wr2
// Also re-zeroes g_cnt[n] for the next replay.
// ---------------------------------------------------------------------------
__global__ void __launch_bounds__(256)
layer2_kernel(const float* __restrict__ Wmix, const float* __restrict__ Wr1,
              const float* __restrict__ wr2, float* __restrict__ out) {
    __shared__ float sW[CC * CC];
    __shared__ float sWr1[CC * HH];
    __shared__ float sw2[HH];
    for (int i = threadIdx.x; i < 256; i += 256) sW[i] = Wmix[2 * 768 + i];
    for (int i = threadIdx.x; i < CC * HH; i += 256) sWr1[i] = Wr1[i];
    if (threadIdx.x < HH) sw2[threadIdx.x] = wr2[threadIdx.x];
    __syncthreads();

    const unsigned FULL = 0xffffffffu;
    int lane  = threadIdx.x & 31;
    int eslot = lane >> 3;
    int q     = lane & 7;
    int n = blockIdx.x * 8 + (threadIdx.x >> 5);

    const float*  xin = g_xs;   // buf0 (layer-1 output)
    const float4* tab = g_Rtab4 + (size_t)2 * TABN * 8;
    const float2* rec = g_rec + (size_t)n * SLOTS;
    int cnt = min(g_cnt[n], SLOTS);
    __syncwarp();
    if (lane == 0) g_cnt[n] = 0;   // reset for next replay (all lanes read cnt already)

    float acc0 = 0.f, acc1 = 0.f;
    if (cnt > 0) aggregate(xin, tab, rec, cnt, eslot, q, acc0, acc1);

    float s0 = 0.f, s1 = 0.f;
#pragma unroll
    for (int cc = 0; cc < 16; cc++) {
        float v = __shfl_sync(FULL, (cc & 1) ? acc1 : acc0, cc >> 1);
        s0 = fmaf(v, sW[cc * 16 + 2 * q],     s0);
        s1 = fmaf(v, sW[cc * 16 + 2 * q + 1], s1);
    }
    float x0 = sspf(s0);   // x[n][2q][0]   (replicated across eslots)
    float x1 = sspf(s1);   // x[n][2q+1][0]

    // readout: lane handles j = 2*lane, 2*lane+1 (all 32 lanes, 64 hidden)
    float h0 = 0.f, h1 = 0.f;
#pragma unroll
    for (int cc = 0; cc < 16; cc++) {
        float v = __shfl_sync(FULL, (cc & 1) ? x1 : x0, cc >> 1);
        h0 = fmaf(v, sWr1[cc * HH + 2 * lane],     h0);
        h1 = fmaf(v, sWr1[cc * HH + 2 * lane + 1], h1);
    }
    float part = sspf(h0) * sw2[2 * lane] + sspf(h1) * sw2[2 * lane + 1];
#pragma unroll
    for (int off = 16; off > 0; off >>= 1)
        part += __shfl_xor_sync(FULL, part, off);
    if (lane == 0) out[n] = part;
}

// ---------------------------------------------------------------------------
extern "C" void kernel_launch(void* const* d_in, const int* in_sizes, int n_in,
                              void* d_out, int out_size) {
    const int*   species = (const int*)d_in[0];
    const int*   eidx    = (const int*)d_in[1];
    const float* dist    = (const float*)d_in[3];
    const float* Wemb    = (const float*)d_in[4];
    const float* W1      = (const float*)d_in[5];
    const float* W2      = (const float*)d_in[6];
    const float* Wmix    = (const float*)d_in[7];
    const float* Wr1     = (const float*)d_in[9];
    const float* wr2     = (const float*)d_in[10];
    float* out = (float*)d_out;

    prep_kernel<<<(PREPTOTAL + 255) / 256, 256>>>(eidx, dist, species, Wemb, W1, W2);
    layer_kernel<<<NN / 8, 256>>>(0, 0, Wmix);   // buf0 -> buf1
    layer_kernel<<<NN / 8, 256>>>(1, 1, Wmix);   // buf1 -> buf0
    layer2_kernel<<<NN / 8, 256>>>(Wmix, Wr1, wr2, out);
}

// round 12
// speedup vs baseline: 1.1468x; 1.1468x over previous
#include <cuda_runtime.h>

#define NN 20000
#define EE 400000
#define CC 16
#define HH 64
#define NB 8
#define NL 3
#define TABN 1024
#define SLOTS 64
#define RMIN 0.5f
#define RCUT 5.0f
#define TABTHREADS (NL * TABN * 32)      // 98304, warp-per-knot
#define PREPTOTAL  (EE + TABTHREADS)     // edge region first (warp-aligned split)

__device__ float  g_xs[2 * NN * CC];               // scalar channel, double buffered
__device__ float4 g_Rtab4[NL * TABN * 8];          // [layer][knot][q]: {Rk[2q],Rk1[2q],Rk[2q+1],Rk1[2q+1]} — 128KB/layer
__device__ int    g_cnt[NN];                       // zero at start of every replay (see layer2)
__device__ float2 g_rec[(size_t)NN * SLOTS];       // {srcoff = src*CC, t}

__device__ __forceinline__ float sspf(float v) {
    // softplus(v) - ln2, fast: |abs err| ~1e-7
    float z = __expf(-fabsf(v));
    return fmaxf(v, 0.f) + __logf(1.f + z) - 0.69314718055994531f;
}

// ---------------------------------------------------------------------------
// Fused prep:
//   tid <  EE : build slotted CSR record {src*CC, t}; first NN*CC threads
//               also init xs buf0 from embedding.
//   tid >= EE : warp per (layer, knot) radial table entry.
// g_cnt is guaranteed zero on entry (static init first run; layer2 re-zeroes).
// ---------------------------------------------------------------------------
__global__ void __launch_bounds__(256)
prep_kernel(const int* __restrict__ eidx, const float* __restrict__ dist,
            const int* __restrict__ species, const float* __restrict__ Wemb,
            const float* __restrict__ W1, const float* __restrict__ W2) {
    int tid = blockIdx.x * 256 + threadIdx.x;

    if (tid < EE) {
        if (tid < NN * CC) {
            int n = tid >> 4, c = tid & 15;
            g_xs[n * CC + c] = Wemb[species[n] * CC + c];
        }
        float r = dist[tid];
        if (!(r < RCUT)) return;
        int src = eidx[2 * tid];
        int dst = eidx[2 * tid + 1];
        int pos = atomicAdd(&g_cnt[dst], 1);
        if (pos >= SLOTS) return;   // statistically unreachable (Poisson ~16.4)
        float t = (r - RMIN) * ((float)(TABN - 1) / (RCUT - RMIN));
        t = fminf(fmaxf(t, 0.f), (float)(TABN - 1) - 1e-3f);
        g_rec[(size_t)dst * SLOTS + pos] = make_float2(__int_as_float(src * CC), t);
        return;
    }

    // ---- table region (whole warps: EE % 32 == 0)
    int gw   = (tid - EE) >> 5;
    int lane = threadIdx.x & 31;
    if (gw >= NL * TABN) return;
    int layer = gw / TABN;
    int k     = gw % TABN;

    __shared__ float sa[8][64];
    float* a = sa[(threadIdx.x >> 5)];

    float r = RMIN + (RCUT - RMIN) * ((float)k / (float)(TABN - 1));
    float u = r / RCUT;
    float u3 = u * u * u;
    float u6 = u3 * u3;
    float env = 1.f - 28.f * u6 + 48.f * u6 * u - 21.f * u6 * u * u;
    if (k == TABN - 1) env = 0.f;
    float pref = sqrtf(2.f / RCUT) / r * env;
    float eb[NB];
#pragma unroll
    for (int n = 0; n < NB; n++)
        eb[n] = pref * sinf((float)(n + 1) * 3.14159265358979323846f * r / RCUT);

    const float* w1 = W1 + (size_t)layer * NB * HH;
    const float* w2 = W2 + (size_t)layer * HH * (2 * CC);
#pragma unroll
    for (int rep = 0; rep < 2; rep++) {
        int j = lane + rep * 32;
        float h = 0.f;
#pragma unroll
        for (int n = 0; n < NB; n++) h = fmaf(eb[n], w1[n * HH + j], h);
        a[j] = sspf(h);
    }
    __syncwarp();

    if (lane < CC) {
        int c = lane;
        float acc = 0.f;
#pragma unroll
        for (int j = 0; j < HH; j++)
            acc = fmaf(a[j], w2[j * 32 + c] + w2[j * 32 + 16 + c], acc);
        float val = acc * 0.22360679774997896f;   // deg_norm = 1/sqrt(20)
        float* T = (float*)(g_Rtab4 + ((size_t)layer * TABN) * 8);
        int q = c >> 1, pos = (c & 1) * 2;
        T[(k * 8 + q) * 4 + pos] = val;                       // Rk[c]
        if (k > 0) T[((k - 1) * 8 + q) * 4 + pos + 1] = val;  // Rk-1's next
    }
}

// ---------------------------------------------------------------------------
// Edge-loop body: records come from SHARED memory (staged by the warp), so
// the dependent chain is smem(29cy) -> tab/xin instead of L2 -> L2.
// lane = eslot*8 + q; 2 independent tab/xin chains in flight (stride 8).
// ---------------------------------------------------------------------------
__device__ __forceinline__ void
aggregate(const float* __restrict__ xin, const float4* __restrict__ tab,
          const float2* srec, int cnt, int eslot, int q,
          float& acc0, float& acc1) {
    float a0 = 0.f, a1 = 0.f, b0 = 0.f, b1 = 0.f;
    int e = eslot;
    for (; e + 4 < cnt; e += 8) {
        float2 rA = srec[e], rB = srec[e + 4];
        int   sA = __float_as_int(rA.x), sB = __float_as_int(rB.x);
        int   kA = (int)rA.y,            kB = (int)rB.y;
        float fA = rA.y - (float)kA,     fB = rB.y - (float)kB;
        float4 pA = tab[kA * 8 + q],     pB = tab[kB * 8 + q];
        const float2 xA = *(const float2*)(xin + sA + 2 * q);
        const float2 xB = *(const float2*)(xin + sB + 2 * q);
        a0 = fmaf(fmaf(fA, pA.y - pA.x, pA.x), xA.x, a0);
        a1 = fmaf(fmaf(fA, pA.w - pA.z, pA.z), xA.y, a1);
        b0 = fmaf(fmaf(fB, pB.y - pB.x, pB.x), xB.x, b0);
        b1 = fmaf(fmaf(fB, pB.w - pB.z, pB.z), xB.y, b1);
    }
    if (e < cnt) {
        float2 rA = srec[e];
        int   sA = __float_as_int(rA.x);
        int   kA = (int)rA.y;
        float fA = rA.y - (float)kA;
        float4 pA = tab[kA * 8 + q];
        const float2 xA = *(const float2*)(xin + sA + 2 * q);
        a0 = fmaf(fmaf(fA, pA.y - pA.x, pA.x), xA.x, a0);
        a1 = fmaf(fmaf(fA, pA.w - pA.z, pA.z), xA.y, a1);
    }
    acc0 = a0 + b0;
    acc1 = a1 + b1;
    // reduce across the 4 edge-slots (lanes q, q+8, q+16, q+24)
    acc0 += __shfl_xor_sync(0xffffffffu, acc0, 8);
    acc1 += __shfl_xor_sync(0xffffffffu, acc1, 8);
    acc0 += __shfl_xor_sync(0xffffffffu, acc0, 16);
    acc1 += __shfl_xor_sync(0xffffffffu, acc1, 16);
}

// Stage this warp's node records into smem (2 coalesced predicated loads).
__device__ __forceinline__ void
stage_rec(float2* srec, const float2* __restrict__ rec, int cnt, int lane) {
    if (lane < cnt) srec[lane] = rec[lane];
    if (lane + 32 < cnt) srec[lane + 32] = rec[lane + 32];
    __syncwarp();
}

// ---------------------------------------------------------------------------
// Scalar layer, warp per node: lanes = 4 edge-slots x 8 channel-pairs.
//   agg[c] = sum_e w_e[c] * xs_in[src_e][c];  xs_out = ssp(agg @ Wmix[l,0])
// ---------------------------------------------------------------------------
__global__ void __launch_bounds__(256)
layer_kernel(int layer, int rd, const float* __restrict__ Wmix) {
    __shared__ float sW[CC * CC];
    __shared__ float2 srecs[8][SLOTS];
    for (int i = threadIdx.x; i < 256; i += 256) sW[i] = Wmix[layer * 768 + i];
    __syncthreads();

    const unsigned FULL = 0xffffffffu;
    int lane  = threadIdx.x & 31;
    int w     = threadIdx.x >> 5;
    int eslot = lane >> 3;
    int q     = lane & 7;
    int n = blockIdx.x * 8 + w;   // NN = 2500 * 8 exactly

    const float*  xin  = g_xs + rd * (NN * CC);
    float*        xout = g_xs + (1 - rd) * (NN * CC);
    const float4* tab  = g_Rtab4 + (size_t)layer * TABN * 8;
    const float2* rec  = g_rec + (size_t)n * SLOTS;
    int cnt = min(g_cnt[n], SLOTS);

    stage_rec(srecs[w], rec, cnt, lane);

    float acc0, acc1;
    aggregate(xin, tab, srecs[w], cnt, eslot, q, acc0, acc1);

    // mix: s[d] = sum_cc agg[cc] * W[cc][d]; agg[cc] lives in lane cc>>1 (eslot0)
    float s0 = 0.f, s1 = 0.f;
#pragma unroll
    for (int cc = 0; cc < 16; cc++) {
        float v = __shfl_sync(FULL, (cc & 1) ? acc1 : acc0, cc >> 1);
        s0 = fmaf(v, sW[cc * 16 + 2 * q],     s0);
        s1 = fmaf(v, sW[cc * 16 + 2 * q + 1], s1);
    }
    if (eslot == 0)
        *(float2*)(xout + n * CC + 2 * q) = make_float2(sspf(s0), sspf(s1));
}

// ---------------------------------------------------------------------------
// Layer 2 fused with readout: out[n] = ssp(ssp(agg@Wmix[2,0]) @ Wr1) @ wr2
// Also re-zeroes g_cnt[n] for the next replay.
// ---------------------------------------------------------------------------
__global__ void __launch_bounds__(256)
layer2_kernel(const float* __restrict__ Wmix, const float* __restrict__ Wr1,
              const float* __restrict__ wr2, float* __restrict__ out) {
    __shared__ float sW[CC * CC];
    __shared__ float sWr1[CC * HH];
    __shared__ float sw2[HH];
    __shared__ float2 srecs[8][SLOTS];
    for (int i = threadIdx.x; i < 256; i += 256) sW[i] = Wmix[2 * 768 + i];
    for (int i = threadIdx.x; i < CC * HH; i += 256) sWr1[i] = Wr1[i];
    if (threadIdx.x < HH) sw2[threadIdx.x] = wr2[threadIdx.x];
    __syncthreads();

    const unsigned FULL = 0xffffffffu;
    int lane  = threadIdx.x & 31;
    int w     = threadIdx.x >> 5;
    int eslot = lane >> 3;
    int q     = lane & 7;
    int n = blockIdx.x * 8 + w;

    const float*  xin = g_xs;   // buf0 (layer-1 output)
    const float4* tab = g_Rtab4 + (size_t)2 * TABN * 8;
    const float2* rec = g_rec + (size_t)n * SLOTS;
    int cnt = min(g_cnt[n], SLOTS);
    __syncwarp();
    if (lane == 0) g_cnt[n] = 0;   // reset for next replay (all lanes read cnt already)

    stage_rec(srecs[w], rec, cnt, lane);

    float acc0, acc1;
    aggregate(xin, tab, srecs[w], cnt, eslot, q, acc0, acc1);

    float s0 = 0.f, s1 = 0.f;
#pragma unroll
    for (int cc = 0; cc < 16; cc++) {
        float v = __shfl_sync(FULL, (cc & 1) ? acc1 : acc0, cc >> 1);
        s0 = fmaf(v, sW[cc * 16 + 2 * q],     s0);
        s1 = fmaf(v, sW[cc * 16 + 2 * q + 1], s1);
    }
    float x0 = sspf(s0);   // x[n][2q][0]   (replicated across eslots)
    float x1 = sspf(s1);   // x[n][2q+1][0]

    // readout: lane handles j = 2*lane, 2*lane+1 (all 32 lanes, 64 hidden)
    float h0 = 0.f, h1 = 0.f;
#pragma unroll
    for (int cc = 0; cc < 16; cc++) {
        float v = __shfl_sync(FULL, (cc & 1) ? x1 : x0, cc >> 1);
        h0 = fmaf(v, sWr1[cc * HH + 2 * lane],     h0);
        h1 = fmaf(v, sWr1[cc * HH + 2 * lane + 1], h1);
    }
    float part = sspf(h0) * sw2[2 * lane] + sspf(h1) * sw2[2 * lane + 1];
#pragma unroll
    for (int off = 16; off > 0; off >>= 1)
        part += __shfl_xor_sync(FULL, part, off);
    if (lane == 0) out[n] = part;
}

// ---------------------------------------------------------------------------
extern "C" void kernel_launch(void* const* d_in, const int* in_sizes, int n_in,
                              void* d_out, int out_size) {
    const int*   species = (const int*)d_in[0];
    const int*   eidx    = (const int*)d_in[1];
    const float* dist    = (const float*)d_in[3];
    const float* Wemb    = (const float*)d_in[4];
    const float* W1      = (const float*)d_in[5];
    const float* W2      = (const float*)d_in[6];
    const float* Wmix    = (const float*)d_in[7];
    const float* Wr1     = (const float*)d_in[9];
    const float* wr2     = (const float*)d_in[10];
    float* out = (float*)d_out;

    prep_kernel<<<(PREPTOTAL + 255) / 256, 256>>>(eidx, dist, species, Wemb, W1, W2);
    layer_kernel<<<NN / 8, 256>>>(0, 0, Wmix);   // buf0 -> buf1
    layer_kernel<<<NN / 8, 256>>>(1, 1, Wmix);   // buf1 -> buf0
    layer2_kernel<<<NN / 8, 256>>>(Wmix, Wr1, wr2, out);
}

// round 13
// speedup vs baseline: 1.1873x; 1.0353x over previous
#include <cuda_runtime.h>

#define NN 20000
#define EE 400000
#define CC 16
#define HH 64
#define NB 8
#define NL 3
#define TABN 1024
#define SLOTS 64
#define RMIN 0.5f
#define RCUT 5.0f
#define TABTHREADS (NL * TABN * 32)      // 98304, warp-per-knot
#define PREPTOTAL  (EE + TABTHREADS)     // edge region first (32-aligned split)
#define NBLK 888                          // 148 SMs x 6 blocks — all co-resident
#define NWARPS (NBLK * 8)

__device__ float  g_xs[2 * NN * CC];               // scalar channel, double buffered
__device__ float4 g_Rtab4[NL * TABN * 8];          // [layer][knot][q]: {Rk[2q],Rk1[2q],Rk[2q+1],Rk1[2q+1]}
__device__ int    g_cnt[NN];                       // zero at start of every replay (phase D resets)
__device__ float2 g_rec[(size_t)NN * SLOTS];       // {srcoff = src*CC, t}
__device__ int    g_bar_cnt;                       // grid barrier state
__device__ volatile int g_bar_gen;

__device__ __forceinline__ float sspf(float v) {
    // softplus(v) - ln2, fast: |abs err| ~1e-7
    float z = __expf(-fabsf(v));
    return fmaxf(v, 0.f) + __logf(1.f + z) - 0.69314718055994531f;
}

__device__ __forceinline__ void grid_barrier() {
    __syncthreads();
    if (threadIdx.x == 0) {
        __threadfence();
        int gen = g_bar_gen;
        if (atomicAdd(&g_bar_cnt, 1) == NBLK - 1) {
            g_bar_cnt = 0;
            __threadfence();
            g_bar_gen = gen + 1;
        } else {
            while (g_bar_gen == gen) __nanosleep(128);
        }
        __threadfence();
    }
    __syncthreads();
}

// ---------------------------------------------------------------------------
// Edge-loop body: records from SHARED memory; lane = eslot*8 + q;
// 2 independent tab/xin chains in flight (stride 8). (R12-proven version.)
// ---------------------------------------------------------------------------
__device__ __forceinline__ void
aggregate(const float* __restrict__ xin, const float4* __restrict__ tab,
          const float2* srec, int cnt, int eslot, int q,
          float& acc0, float& acc1) {
    float a0 = 0.f, a1 = 0.f, b0 = 0.f, b1 = 0.f;
    int e = eslot;
    for (; e + 4 < cnt; e += 8) {
        float2 rA = srec[e], rB = srec[e + 4];
        int   sA = __float_as_int(rA.x), sB = __float_as_int(rB.x);
        int   kA = (int)rA.y,            kB = (int)rB.y;
        float fA = rA.y - (float)kA,     fB = rB.y - (float)kB;
        float4 pA = tab[kA * 8 + q],     pB = tab[kB * 8 + q];
        const float2 xA = *(const float2*)(xin + sA + 2 * q);
        const float2 xB = *(const float2*)(xin + sB + 2 * q);
        a0 = fmaf(fmaf(fA, pA.y - pA.x, pA.x), xA.x, a0);
        a1 = fmaf(fmaf(fA, pA.w - pA.z, pA.z), xA.y, a1);
        b0 = fmaf(fmaf(fB, pB.y - pB.x, pB.x), xB.x, b0);
        b1 = fmaf(fmaf(fB, pB.w - pB.z, pB.z), xB.y, b1);
    }
    if (e < cnt) {
        float2 rA = srec[e];
        int   sA = __float_as_int(rA.x);
        int   kA = (int)rA.y;
        float fA = rA.y - (float)kA;
        float4 pA = tab[kA * 8 + q];
        const float2 xA = *(const float2*)(xin + sA + 2 * q);
        a0 = fmaf(fmaf(fA, pA.y - pA.x, pA.x), xA.x, a0);
        a1 = fmaf(fmaf(fA, pA.w - pA.z, pA.z), xA.y, a1);
    }
    acc0 = a0 + b0;
    acc1 = a1 + b1;
    acc0 += __shfl_xor_sync(0xffffffffu, acc0, 8);
    acc1 += __shfl_xor_sync(0xffffffffu, acc1, 8);
    acc0 += __shfl_xor_sync(0xffffffffu, acc0, 16);
    acc1 += __shfl_xor_sync(0xffffffffu, acc1, 16);
}

__device__ __forceinline__ void
stage_rec(float2* srec, const float2* __restrict__ rec, int cnt, int lane) {
    if (lane < cnt) srec[lane] = rec[lane];
    if (lane + 32 < cnt) srec[lane + 32] = rec[lane + 32];
    __syncwarp();
}

// ---------------------------------------------------------------------------
// One persistent kernel: phase A prep -> B layer0 -> C layer1 -> D layer2+readout
// ---------------------------------------------------------------------------
__global__ void __launch_bounds__(256, 6)
fused_kernel(const int* __restrict__ eidx, const float* __restrict__ dist,
             const int* __restrict__ species, const float* __restrict__ Wemb,
             const float* __restrict__ W1, const float* __restrict__ W2,
             const float* __restrict__ Wmix, const float* __restrict__ Wr1,
             const float* __restrict__ wr2, float* __restrict__ out) {
    __shared__ float  sW[NL * CC * CC];   // scalar-mix blocks of all 3 layers
    __shared__ float  sWr1[CC * HH];
    __shared__ float  sw2[HH];
    __shared__ float2 srecs[8][SLOTS];
    __shared__ float  sa[8][64];

    for (int i = threadIdx.x; i < NL * 256; i += 256) {
        int l = i >> 8, r = i & 255;
        sW[i] = Wmix[l * 768 + r];
    }
    for (int i = threadIdx.x; i < CC * HH; i += 256) sWr1[i] = Wr1[i];
    if (threadIdx.x < HH) sw2[threadIdx.x] = wr2[threadIdx.x];
    __syncthreads();

    const unsigned FULL = 0xffffffffu;
    int lane  = threadIdx.x & 31;
    int w     = threadIdx.x >> 5;
    int eslot = lane >> 3;
    int q     = lane & 7;
    int gwarp = blockIdx.x * 8 + w;
    float2* srec = srecs[w];

    // ======== Phase A: edges + embedding + radial tables ====================
    for (int tid = blockIdx.x * 256 + threadIdx.x; tid < PREPTOTAL; tid += NBLK * 256) {
        if (tid < EE) {
            if (tid < NN * CC) {
                int n = tid >> 4, c = tid & 15;
                g_xs[n * CC + c] = Wemb[species[n] * CC + c];
            }
            float r = dist[tid];
            if (r < RCUT) {
                int src = eidx[2 * tid];
                int dst = eidx[2 * tid + 1];
                int pos = atomicAdd(&g_cnt[dst], 1);
                if (pos < SLOTS) {
                    float t = (r - RMIN) * ((float)(TABN - 1) / (RCUT - RMIN));
                    t = fminf(fmaxf(t, 0.f), (float)(TABN - 1) - 1e-3f);
                    g_rec[(size_t)dst * SLOTS + pos] =
                        make_float2(__int_as_float(src * CC), t);
                }
            }
        } else {
            // table region: whole warps (EE and stride are 32-aligned)
            int gw2   = (tid - EE) >> 5;
            int layer = gw2 / TABN;
            int k     = gw2 % TABN;
            float* a = sa[w];

            float r = RMIN + (RCUT - RMIN) * ((float)k / (float)(TABN - 1));
            float u = r / RCUT;
            float u3 = u * u * u;
            float u6 = u3 * u3;
            float env = 1.f - 28.f * u6 + 48.f * u6 * u - 21.f * u6 * u * u;
            if (k == TABN - 1) env = 0.f;
            float pref = sqrtf(2.f / RCUT) / r * env;
            float eb[NB];
#pragma unroll
            for (int n = 0; n < NB; n++)
                eb[n] = pref * sinf((float)(n + 1) * 3.14159265358979323846f * r / RCUT);

            const float* w1 = W1 + (size_t)layer * NB * HH;
            const float* w2p = W2 + (size_t)layer * HH * (2 * CC);
#pragma unroll
            for (int rep = 0; rep < 2; rep++) {
                int j = lane + rep * 32;
                float h = 0.f;
#pragma unroll
                for (int n = 0; n < NB; n++) h = fmaf(eb[n], w1[n * HH + j], h);
                a[j] = sspf(h);
            }
            __syncwarp();

            if (lane < CC) {
                int c = lane;
                float acc = 0.f;
#pragma unroll
                for (int j = 0; j < HH; j++)
                    acc = fmaf(a[j], w2p[j * 32 + c] + w2p[j * 32 + 16 + c], acc);
                float val = acc * 0.22360679774997896f;   // 1/sqrt(20)
                float* T = (float*)(g_Rtab4 + ((size_t)layer * TABN) * 8);
                int qq = c >> 1, pos = (c & 1) * 2;
                T[(k * 8 + qq) * 4 + pos] = val;
                if (k > 0) T[((k - 1) * 8 + qq) * 4 + pos + 1] = val;
            }
            __syncwarp();
        }
    }

    grid_barrier();

    // ======== Phases B, C: layers 0 and 1 ==================================
#pragma unroll
    for (int layer = 0; layer < 2; layer++) {
        const float*  xin  = g_xs + (layer & 1) * (NN * CC);
        float*        xout = g_xs + ((layer + 1) & 1) * (NN * CC);
        const float4* tab  = g_Rtab4 + (size_t)layer * TABN * 8;
        const float*  sWl  = sW + layer * 256;
        for (int n = gwarp; n < NN; n += NWARPS) {
            const float2* rec = g_rec + (size_t)n * SLOTS;
            int cnt = min(g_cnt[n], SLOTS);
            stage_rec(srec, rec, cnt, lane);
            float acc0, acc1;
            aggregate(xin, tab, srec, cnt, eslot, q, acc0, acc1);
            float s0 = 0.f, s1 = 0.f;
#pragma unroll
            for (int cc = 0; cc < 16; cc++) {
                float v = __shfl_sync(FULL, (cc & 1) ? acc1 : acc0, cc >> 1);
                s0 = fmaf(v, sWl[cc * 16 + 2 * q],     s0);
                s1 = fmaf(v, sWl[cc * 16 + 2 * q + 1], s1);
            }
            if (eslot == 0)
                *(float2*)(xout + n * CC + 2 * q) = make_float2(sspf(s0), sspf(s1));
            __syncwarp();
        }
        grid_barrier();
    }

    // ======== Phase D: layer 2 + readout, reset g_cnt ======================
    {
        const float*  xin = g_xs;                    // buf0 (layer-1 output)
        const float4* tab = g_Rtab4 + (size_t)2 * TABN * 8;
        const float*  sWl = sW + 2 * 256;
        for (int n = gwarp; n < NN; n += NWARPS) {
            const float2* rec = g_rec + (size_t)n * SLOTS;
            int cnt = min(g_cnt[n], SLOTS);
            __syncwarp();
            if (lane == 0) g_cnt[n] = 0;             // reset for next replay
            stage_rec(srec, rec, cnt, lane);
            float acc0, acc1;
            aggregate(xin, tab, srec, cnt, eslot, q, acc0, acc1);
            float s0 = 0.f, s1 = 0.f;
#pragma unroll
            for (int cc = 0; cc < 16; cc++) {
                float v = __shfl_sync(FULL, (cc & 1) ? acc1 : acc0, cc >> 1);
                s0 = fmaf(v, sWl[cc * 16 + 2 * q],     s0);
                s1 = fmaf(v, sWl[cc * 16 + 2 * q + 1], s1);
            }
            float x0 = sspf(s0);
            float x1 = sspf(s1);
            float h0 = 0.f, h1 = 0.f;
#pragma unroll
            for (int cc = 0; cc < 16; cc++) {
                float v = __shfl_sync(FULL, (cc & 1) ? x1 : x0, cc >> 1);
                h0 = fmaf(v, sWr1[cc * HH + 2 * lane],     h0);
                h1 = fmaf(v, sWr1[cc * HH + 2 * lane + 1], h1);
            }
            float part = sspf(h0) * sw2[2 * lane] + sspf(h1) * sw2[2 * lane + 1];
#pragma unroll
            for (int off = 16; off > 0; off >>= 1)
                part += __shfl_xor_sync(FULL, part, off);
            if (lane == 0) out[n] = part;
            __syncwarp();
        }
    }
}

// ---------------------------------------------------------------------------
extern "C" void kernel_launch(void* const* d_in, const int* in_sizes, int n_in,
                              void* d_out, int out_size) {
    const int*   species = (const int*)d_in[0];
    const int*   eidx    = (const int*)d_in[1];
    const float* dist    = (const float*)d_in[3];
    const float* Wemb    = (const float*)d_in[4];
    const float* W1      = (const float*)d_in[5];
    const float* W2      = (const float*)d_in[6];
    const float* Wmix    = (const float*)d_in[7];
    const float* Wr1     = (const float*)d_in[9];
    const float* wr2     = (const float*)d_in[10];
    float* out = (float*)d_out;

    fused_kernel<<<NBLK, 256>>>(eidx, dist, species, Wemb, W1, W2,
                                Wmix, Wr1, wr2, out);
}

// round 14
// speedup vs baseline: 1.1928x; 1.0046x over previous
#include <cuda_runtime.h>

#define NN 20000
#define EE 400000
#define CC 16
#define HH 64
#define NB 8
#define NL 3
#define TABN 1024
#define SLOTS 64
#define RMIN 0.5f
#define RCUT 5.0f
#define TABTHREADS (NL * TABN * 32)      // 98304, warp-per-knot
#define PREPTOTAL  (EE + TABTHREADS)     // edge region first (32-aligned split)
#define BPSM 7
#define NBLK (148 * BPSM)                 // all co-resident (grid barrier relies on it)
#define NWARPS (NBLK * 8)

__device__ float  g_xs[2 * NN * CC];               // scalar channel, double buffered
__device__ float4 g_Rtab4[NL * TABN * 8];          // [layer][knot][q]: {Rk[2q],Rk1[2q],Rk[2q+1],Rk1[2q+1]}
__device__ int    g_cnt[NN];                       // zero at start of every replay (phase D resets)
__device__ float2 g_rec[(size_t)NN * SLOTS];       // {srcoff = src*CC, t}
__device__ int    g_bar_cnt;                       // grid barrier state
__device__ volatile int g_bar_gen;

__device__ __forceinline__ float sspf(float v) {
    // softplus(v) - ln2, fast: |abs err| ~1e-7
    float z = __expf(-fabsf(v));
    return fmaxf(v, 0.f) + __logf(1.f + z) - 0.69314718055994531f;
}

__device__ __forceinline__ void grid_barrier() {
    __syncthreads();
    if (threadIdx.x == 0) {
        __threadfence();
        int gen = g_bar_gen;
        if (atomicAdd(&g_bar_cnt, 1) == NBLK - 1) {
            g_bar_cnt = 0;
            __threadfence();
            g_bar_gen = gen + 1;
        } else {
            while (g_bar_gen == gen) __nanosleep(64);
        }
        __threadfence();
    }
    __syncthreads();
}

// ---------------------------------------------------------------------------
// Edge-loop body: records from SHARED memory; lane = eslot*8 + q;
// 2 independent tab/xin chains in flight (stride 8). (R12-proven version.)
// ---------------------------------------------------------------------------
__device__ __forceinline__ void
aggregate(const float* __restrict__ xin, const float4* __restrict__ tab,
          const float2* srec, int cnt, int eslot, int q,
          float& acc0, float& acc1) {
    float a0 = 0.f, a1 = 0.f, b0 = 0.f, b1 = 0.f;
    int e = eslot;
    for (; e + 4 < cnt; e += 8) {
        float2 rA = srec[e], rB = srec[e + 4];
        int   sA = __float_as_int(rA.x), sB = __float_as_int(rB.x);
        int   kA = (int)rA.y,            kB = (int)rB.y;
        float fA = rA.y - (float)kA,     fB = rB.y - (float)kB;
        float4 pA = tab[kA * 8 + q],     pB = tab[kB * 8 + q];
        const float2 xA = *(const float2*)(xin + sA + 2 * q);
        const float2 xB = *(const float2*)(xin + sB + 2 * q);
        a0 = fmaf(fmaf(fA, pA.y - pA.x, pA.x), xA.x, a0);
        a1 = fmaf(fmaf(fA, pA.w - pA.z, pA.z), xA.y, a1);
        b0 = fmaf(fmaf(fB, pB.y - pB.x, pB.x), xB.x, b0);
        b1 = fmaf(fmaf(fB, pB.w - pB.z, pB.z), xB.y, b1);
    }
    if (e < cnt) {
        float2 rA = srec[e];
        int   sA = __float_as_int(rA.x);
        int   kA = (int)rA.y;
        float fA = rA.y - (float)kA;
        float4 pA = tab[kA * 8 + q];
        const float2 xA = *(const float2*)(xin + sA + 2 * q);
        a0 = fmaf(fmaf(fA, pA.y - pA.x, pA.x), xA.x, a0);
        a1 = fmaf(fmaf(fA, pA.w - pA.z, pA.z), xA.y, a1);
    }
    acc0 = a0 + b0;
    acc1 = a1 + b1;
    acc0 += __shfl_xor_sync(0xffffffffu, acc0, 8);
    acc1 += __shfl_xor_sync(0xffffffffu, acc1, 8);
    acc0 += __shfl_xor_sync(0xffffffffu, acc0, 16);
    acc1 += __shfl_xor_sync(0xffffffffu, acc1, 16);
}

__device__ __forceinline__ void
stage_rec(float2* srec, const float2* __restrict__ rec, int cnt, int lane) {
    if (lane < cnt) srec[lane] = rec[lane];
    if (lane + 32 < cnt) srec[lane + 32] = rec[lane + 32];
    __syncwarp();
}

// ---------------------------------------------------------------------------
// One persistent kernel: phase A prep -> B layer0 -> C layer1 -> D layer2+readout
// ---------------------------------------------------------------------------
__global__ void __launch_bounds__(256, BPSM)
fused_kernel(const int* __restrict__ eidx, const float* __restrict__ dist,
             const int* __restrict__ species, const float* __restrict__ Wemb,
             const float* __restrict__ W1, const float* __restrict__ W2,
             const float* __restrict__ Wmix, const float* __restrict__ Wr1,
             const float* __restrict__ wr2, float* __restrict__ out) {
    __shared__ float  sW[NL * CC * CC];   // scalar-mix blocks of all 3 layers
    __shared__ float  sWr1[CC * HH];
    __shared__ float  sw2[HH];
    // sa (phase A only) aliases srecs (phases B-D only)
    __shared__ union {
        float2 srecs[8][SLOTS];
        float  sa[8][64];
    } sh;

    for (int i = threadIdx.x; i < NL * 256; i += 256) {
        int l = i >> 8, r = i & 255;
        sW[i] = Wmix[l * 768 + r];
    }
    for (int i = threadIdx.x; i < CC * HH; i += 256) sWr1[i] = Wr1[i];
    if (threadIdx.x < HH) sw2[threadIdx.x] = wr2[threadIdx.x];
    __syncthreads();

    const unsigned FULL = 0xffffffffu;
    int lane  = threadIdx.x & 31;
    int w     = threadIdx.x >> 5;
    int eslot = lane >> 3;
    int q     = lane & 7;
    int gwarp = blockIdx.x * 8 + w;
    float2* srec = sh.srecs[w];

    // ======== Phase A: edges + embedding + radial tables ====================
    for (int tid = blockIdx.x * 256 + threadIdx.x; tid < PREPTOTAL; tid += NBLK * 256) {
        if (tid < EE) {
            if (tid < NN * CC) {
                int n = tid >> 4, c = tid & 15;
                g_xs[n * CC + c] = Wemb[species[n] * CC + c];
            }
            float r = dist[tid];
            if (r < RCUT) {
                int src = eidx[2 * tid];
                int dst = eidx[2 * tid + 1];
                int pos = atomicAdd(&g_cnt[dst], 1);
                if (pos < SLOTS) {
                    float t = (r - RMIN) * ((float)(TABN - 1) / (RCUT - RMIN));
                    t = fminf(fmaxf(t, 0.f), (float)(TABN - 1) - 1e-3f);
                    g_rec[(size_t)dst * SLOTS + pos] =
                        make_float2(__int_as_float(src * CC), t);
                }
            }
        } else {
            // table region: whole warps (EE and stride are 32-aligned)
            int gw2   = (tid - EE) >> 5;
            int layer = gw2 / TABN;
            int k     = gw2 % TABN;
            float* a = sh.sa[w];

            float r = RMIN + (RCUT - RMIN) * ((float)k / (float)(TABN - 1));
            float u = r / RCUT;
            float u3 = u * u * u;
            float u6 = u3 * u3;
            float env = 1.f - 28.f * u6 + 48.f * u6 * u - 21.f * u6 * u * u;
            if (k == TABN - 1) env = 0.f;
            float pref = sqrtf(2.f / RCUT) / r * env;
            float eb[NB];
#pragma unroll
            for (int n = 0; n < NB; n++)
                eb[n] = pref * sinf((float)(n + 1) * 3.14159265358979323846f * r / RCUT);

            const float* w1 = W1 + (size_t)layer * NB * HH;
            const float* w2p = W2 + (size_t)layer * HH * (2 * CC);
#pragma unroll
            for (int rep = 0; rep < 2; rep++) {
                int j = lane + rep * 32;
                float h = 0.f;
#pragma unroll
                for (int n = 0; n < NB; n++) h = fmaf(eb[n], w1[n * HH + j], h);
                a[j] = sspf(h);
            }
            __syncwarp();

            if (lane < CC) {
                int c = lane;
                float acc = 0.f;
#pragma unroll
                for (int j = 0; j < HH; j++)
                    acc = fmaf(a[j], w2p[j * 32 + c] + w2p[j * 32 + 16 + c], acc);
                float val = acc * 0.22360679774997896f;   // 1/sqrt(20)
                float* T = (float*)(g_Rtab4 + ((size_t)layer * TABN) * 8);
                int qq = c >> 1, pos = (c & 1) * 2;
                T[(k * 8 + qq) * 4 + pos] = val;
                if (k > 0) T[((k - 1) * 8 + qq) * 4 + pos + 1] = val;
            }
            __syncwarp();
        }
    }

    grid_barrier();

    // ======== Phases B, C: layers 0 and 1 ==================================
#pragma unroll
    for (int layer = 0; layer < 2; layer++) {
        const float*  xin  = g_xs + (layer & 1) * (NN * CC);
        float*        xout = g_xs + ((layer + 1) & 1) * (NN * CC);
        const float4* tab  = g_Rtab4 + (size_t)layer * TABN * 8;
        const float*  sWl  = sW + layer * 256;
        for (int n = gwarp; n < NN; n += NWARPS) {
            const float2* rec = g_rec + (size_t)n * SLOTS;
            int cnt = min(g_cnt[n], SLOTS);
            stage_rec(srec, rec, cnt, lane);
            float acc0, acc1;
            aggregate(xin, tab, srec, cnt, eslot, q, acc0, acc1);
            float s0 = 0.f, s1 = 0.f;
#pragma unroll
            for (int cc = 0; cc < 16; cc++) {
                float v = __shfl_sync(FULL, (cc & 1) ? acc1 : acc0, cc >> 1);
                s0 = fmaf(v, sWl[cc * 16 + 2 * q],     s0);
                s1 = fmaf(v, sWl[cc * 16 + 2 * q + 1], s1);
            }
            if (eslot == 0)
                *(float2*)(xout + n * CC + 2 * q) = make_float2(sspf(s0), sspf(s1));
            __syncwarp();
        }
        grid_barrier();
    }

    // ======== Phase D: layer 2 + readout, reset g_cnt ======================
    {
        const float*  xin = g_xs;                    // buf0 (layer-1 output)
        const float4* tab = g_Rtab4 + (size_t)2 * TABN * 8;
        const float*  sWl = sW + 2 * 256;
        for (int n = gwarp; n < NN; n += NWARPS) {
            const float2* rec = g_rec + (size_t)n * SLOTS;
            int cnt = min(g_cnt[n], SLOTS);
            __syncwarp();
            if (lane == 0) g_cnt[n] = 0;             // reset for next replay
            stage_rec(srec, rec, cnt, lane);
            float acc0, acc1;
            aggregate(xin, tab, srec, cnt, eslot, q, acc0, acc1);
            float s0 = 0.f, s1 = 0.f;
#pragma unroll
            for (int cc = 0; cc < 16; cc++) {
                float v = __shfl_sync(FULL, (cc & 1) ? acc1 : acc0, cc >> 1);
                s0 = fmaf(v, sWl[cc * 16 + 2 * q],     s0);
                s1 = fmaf(v, sWl[cc * 16 + 2 * q + 1], s1);
            }
            float x0 = sspf(s0);
            float x1 = sspf(s1);
            float h0 = 0.f, h1 = 0.f;
#pragma unroll
            for (int cc = 0; cc < 16; cc++) {
                float v = __shfl_sync(FULL, (cc & 1) ? x1 : x0, cc >> 1);
                h0 = fmaf(v, sWr1[cc * HH + 2 * lane],     h0);
                h1 = fmaf(v, sWr1[cc * HH + 2 * lane + 1], h1);
            }
            float part = sspf(h0) * sw2[2 * lane] + sspf(h1) * sw2[2 * lane + 1];
#pragma unroll
            for (int off = 16; off > 0; off >>= 1)
                part += __shfl_xor_sync(FULL, part, off);
            if (lane == 0) out[n] = part;
            __syncwarp();
        }
    }
}

// ---------------------------------------------------------------------------
extern "C" void kernel_launch(void* const* d_in, const int* in_sizes, int n_in,
                              void* d_out, int out_size) {
    const int*   species = (const int*)d_in[0];
    const int*   eidx    = (const int*)d_in[1];
    const float* dist    = (const float*)d_in[3];
    const float* Wemb    = (const float*)d_in[4];
    const float* W1      = (const float*)d_in[5];
    const float* W2      = (const float*)d_in[6];
    const float* Wmix    = (const float*)d_in[7];
    const float* Wr1     = (const float*)d_in[9];
    const float* wr2     = (const float*)d_in[10];
    float* out = (float*)d_out;

    fused_kernel<<<NBLK, 256>>>(eidx, dist, species, Wemb, W1, W2,
                                Wmix, Wr1, wr2, out);
}